// round 1
// baseline (speedup 1.0000x reference)
#include <cuda_runtime.h>
#include <cuda_bf16.h>

#define B_ 4
#define H_ 16
#define NQ 256
#define D_ 16

// Scratch for projected Q/K/V in [b][h][n][d] layout (no runtime allocation allowed).
__device__ float g_Q[B_ * H_ * NQ * D_];
__device__ float g_K[B_ * H_ * NQ * D_];
__device__ float g_V[B_ * H_ * NQ * D_];

// ---------------------------------------------------------------------------
// Kernel A: QKV projections.  out[m, hd] = sum_e A[m, e] * W[hd, e]
// (A and W are both row-major with K (=e) contiguous, so loads are coalesced.)
// Tiled 64x64, 256 threads, 4x4 micro-tile per thread, K-step 16.
// Writes directly into [b][h][n][d] scratch layout.
// ---------------------------------------------------------------------------
__global__ __launch_bounds__(256) void qkv_kernel(
    const float* __restrict__ row_emb, const float* __restrict__ col_emb,
    const float* __restrict__ Wq, const float* __restrict__ Wk,
    const float* __restrict__ Wv)
{
    __shared__ float As[16][68];   // [k][m], padded
    __shared__ float Ws[16][68];   // [k][n], padded

    const float* A; const float* W; float* O;
    int z = blockIdx.z;
    if (z == 0)      { A = row_emb; W = Wq; O = g_Q; }
    else if (z == 1) { A = col_emb; W = Wk; O = g_K; }
    else             { A = col_emb; W = Wv; O = g_V; }

    int m0 = blockIdx.y * 64;      // row tile (m = b*256 + n)
    int n0 = blockIdx.x * 64;      // col tile (hd)
    int t  = threadIdx.x;
    int tx = t & 15, ty = t >> 4;
    int lm = t >> 2, lk = (t & 3) * 4;   // load mapping: 64 rows x 16 k

    float acc[4][4];
    #pragma unroll
    for (int i = 0; i < 4; i++)
        #pragma unroll
        for (int j = 0; j < 4; j++) acc[i][j] = 0.f;

    for (int k0 = 0; k0 < 256; k0 += 16) {
        float4 av = *(const float4*)&A[(m0 + lm) * 256 + k0 + lk];
        float4 wv = *(const float4*)&W[(n0 + lm) * 256 + k0 + lk];
        __syncthreads();
        As[lk + 0][lm] = av.x; As[lk + 1][lm] = av.y;
        As[lk + 2][lm] = av.z; As[lk + 3][lm] = av.w;
        Ws[lk + 0][lm] = wv.x; Ws[lk + 1][lm] = wv.y;
        Ws[lk + 2][lm] = wv.z; Ws[lk + 3][lm] = wv.w;
        __syncthreads();
        #pragma unroll
        for (int k = 0; k < 16; k++) {
            float4 a  = *(const float4*)&As[k][ty * 4];
            float4 bq = *(const float4*)&Ws[k][tx * 4];
            float am[4] = {a.x, a.y, a.z, a.w};
            float bm[4] = {bq.x, bq.y, bq.z, bq.w};
            #pragma unroll
            for (int i = 0; i < 4; i++)
                #pragma unroll
                for (int j = 0; j < 4; j++)
                    acc[i][j] = fmaf(am[i], bm[j], acc[i][j]);
        }
    }

    // Scatter into [b][h][n][d] layout.  h,d constant per thread; b constant
    // per tile (64 | 256).
    int bb = (m0) >> 8;
    int hh = (n0 >> 4) + (tx >> 2);
    int dd = (tx & 3) * 4;
    #pragma unroll
    for (int i = 0; i < 4; i++) {
        int m = m0 + ty * 4 + i;
        int r = m & 255;
        float4 o = make_float4(acc[i][0], acc[i][1], acc[i][2], acc[i][3]);
        *(float4*)&O[((bb * H_ + hh) * NQ + r) * D_ + dd] = o;
    }
}

// ---------------------------------------------------------------------------
// Kernel B: fused scores + mixing-MLP + softmax + AV.
// One block per (b, h, 8-row tile); one warp per row; each lane owns 8 columns.
// K/V tiles live in shared (row stride 20 -> conflict-free LDS.128).
// mix2_bias is dropped: it is a per-row constant and softmax-invariant.
// ---------------------------------------------------------------------------
__global__ __launch_bounds__(256) void attn_kernel(
    const float* __restrict__ cost_mat,
    const float* __restrict__ mix1_w,   // [16][2][32]
    const float* __restrict__ mix1_b,   // [16][32]
    const float* __restrict__ mix2_w,   // [16][32][1]
    float* __restrict__ out)            // [B][R][H*D]
{
    __shared__ float  Ks[256][20];
    __shared__ float  Vs[256][20];
    __shared__ float4 mlp[32];          // (w1_dot, w1_cost, bias1, w2)

    int b = blockIdx.z, h = blockIdx.y, rt = blockIdx.x;
    int bh = b * H_ + h;
    int t = threadIdx.x;
    int lane = t & 31, w = t >> 5;

    // Cooperative load of K,V tiles (one row per thread, 64B contiguous each).
    {
        const float* Kg = g_K + bh * NQ * D_;
        const float* Vg = g_V + bh * NQ * D_;
        int c = t;
        #pragma unroll
        for (int j = 0; j < 4; j++) {
            *(float4*)&Ks[c][j * 4] = *(const float4*)&Kg[c * D_ + j * 4];
            *(float4*)&Vs[c][j * 4] = *(const float4*)&Vg[c * D_ + j * 4];
        }
    }
    if (t < 32) {
        mlp[t] = make_float4(mix1_w[h * 64 + t],        // weight on dot_score
                             mix1_w[h * 64 + 32 + t],   // weight on cost_score
                             mix1_b[h * 32 + t],
                             mix2_w[h * 32 + t]);
    }
    __syncthreads();

    int r = rt * 8 + w;

    // Broadcast-load this row's q into registers.
    float q[16];
    {
        const float* Qg = g_Q + (bh * NQ + r) * D_;
        #pragma unroll
        for (int j = 0; j < 4; j++) {
            float4 qv = *(const float4*)&Qg[j * 4];
            q[j * 4 + 0] = qv.x; q[j * 4 + 1] = qv.y;
            q[j * 4 + 2] = qv.z; q[j * 4 + 3] = qv.w;
        }
    }
    const float* costRow = cost_mat + (b * NQ + r) * NQ;

    // Phase 1: dot scores (scaled) + cost loads, 8 columns per lane.
    float dotv[8], costv[8];
    #pragma unroll
    for (int i = 0; i < 8; i++) {
        int c = i * 32 + lane;
        float s = 0.f;
        #pragma unroll
        for (int j = 0; j < 4; j++) {
            float4 kv = *(const float4*)&Ks[c][j * 4];
            s = fmaf(q[j * 4 + 0], kv.x, s);
            s = fmaf(q[j * 4 + 1], kv.y, s);
            s = fmaf(q[j * 4 + 2], kv.z, s);
            s = fmaf(q[j * 4 + 3], kv.w, s);
        }
        dotv[i]  = s * 0.25f;            // 1/sqrt(16)
        costv[i] = __ldg(&costRow[c]);
    }

    // Phase 2: mixing MLP, m-outer so each weight vector loads once.
    float sc[8];
    #pragma unroll
    for (int i = 0; i < 8; i++) sc[i] = 0.f;
    #pragma unroll 4
    for (int m = 0; m < 32; m++) {
        float4 wv = mlp[m];
        #pragma unroll
        for (int i = 0; i < 8; i++) {
            float tm = fmaf(wv.y, costv[i], wv.z);
            tm = fmaf(wv.x, dotv[i], tm);
            tm = fmaxf(tm, 0.f);
            sc[i] = fmaf(wv.w, tm, sc[i]);
        }
    }

    // Phase 3: softmax over 256 columns (8 per lane + warp reduce).
    float mx = sc[0];
    #pragma unroll
    for (int i = 1; i < 8; i++) mx = fmaxf(mx, sc[i]);
    #pragma unroll
    for (int o = 16; o; o >>= 1) mx = fmaxf(mx, __shfl_xor_sync(0xffffffffu, mx, o));
    float sum = 0.f;
    #pragma unroll
    for (int i = 0; i < 8; i++) { sc[i] = __expf(sc[i] - mx); sum += sc[i]; }
    #pragma unroll
    for (int o = 16; o; o >>= 1) sum += __shfl_xor_sync(0xffffffffu, sum, o);
    float inv = 1.f / sum;

    // Phase 4: AV accumulation (unnormalized; divide at the end).
    float acc[16];
    #pragma unroll
    for (int d = 0; d < 16; d++) acc[d] = 0.f;
    #pragma unroll
    for (int i = 0; i < 8; i++) {
        int c = i * 32 + lane;
        float wg = sc[i];
        #pragma unroll
        for (int j = 0; j < 4; j++) {
            float4 vv = *(const float4*)&Vs[c][j * 4];
            acc[j * 4 + 0] = fmaf(wg, vv.x, acc[j * 4 + 0]);
            acc[j * 4 + 1] = fmaf(wg, vv.y, acc[j * 4 + 1]);
            acc[j * 4 + 2] = fmaf(wg, vv.z, acc[j * 4 + 2]);
            acc[j * 4 + 3] = fmaf(wg, vv.w, acc[j * 4 + 3]);
        }
    }

    // Cross-lane reduce: 16 butterfly chains; lane d keeps value d (static idx).
    float res = 0.f;
    #pragma unroll
    for (int d = 0; d < 16; d++) {
        float s = acc[d];
        #pragma unroll
        for (int o = 16; o; o >>= 1) s += __shfl_xor_sync(0xffffffffu, s, o);
        if (lane == d) res = s;
    }
    if (lane < 16)
        out[(b * NQ + r) * (H_ * D_) + h * D_ + lane] = res * inv;
}

extern "C" void kernel_launch(void* const* d_in, const int* in_sizes, int n_in,
                              void* d_out, int out_size)
{
    const float* row_emb  = (const float*)d_in[0];
    const float* col_emb  = (const float*)d_in[1];
    const float* cost_mat = (const float*)d_in[2];
    const float* Wq       = (const float*)d_in[3];
    const float* Wk       = (const float*)d_in[4];
    const float* Wv       = (const float*)d_in[5];
    const float* m1w      = (const float*)d_in[6];
    const float* m1b      = (const float*)d_in[7];
    const float* m2w      = (const float*)d_in[8];
    // d_in[9] = mix2_bias: softmax-invariant, intentionally unused.
    float* out = (float*)d_out;

    dim3 gA(4, 16, 3);   // n-tiles x m-tiles x {Q,K,V}
    qkv_kernel<<<gA, 256>>>(row_emb, col_emb, Wq, Wk, Wv);

    dim3 gB(32, 16, 4);  // row-tiles x heads x batch
    attn_kernel<<<gB, 256>>>(cost_mat, m1w, m1b, m2w, out);
}